// round 13
// baseline (speedup 1.0000x reference)
#include <cuda_runtime.h>
#include <cuda_bf16.h>
#include <cstdint>

#define D_MODEL 1024
#define HEADS   16
#define HD      64
#define BB      2
#define TT      2048
#define MTOT    (BB*TT)

// ---------------- GEMM config ----------------
#define GKC   32
#define GNCH  (D_MODEL/GKC)
#define GOP   8192
#define GSTG  (4*GOP)
#define GEMM_SMEM (3*GSTG)

// ---------------- attention config (2-stage, occ 2, 2 heads/CTA) --------
#define AQT   16384
#define AKT   8192
#define ASTG  (4*AKT)
#define ATTN_SMEM (2*AQT + 2*ASTG)   // 98304
#define NKT   (TT/64)

// ---------------- cvt config ----------------
#define N4A (MTOT*D_MODEL/4)
#define N4W (D_MODEL*D_MODEL/4)
#define CVT_BLOCKS ((3*N4A + 4*N4W)/256)
#define SCL_BLOCKS (MTOT/256)

// -------- scratch (device globals; allocations forbidden) --------
__device__ __nv_bfloat16 g_xq_hi[(size_t)MTOT*D_MODEL], g_xq_lo[(size_t)MTOT*D_MODEL];
__device__ __nv_bfloat16 g_xk_hi[(size_t)MTOT*D_MODEL], g_xk_lo[(size_t)MTOT*D_MODEL];
__device__ __nv_bfloat16 g_xv_hi[(size_t)MTOT*D_MODEL], g_xv_lo[(size_t)MTOT*D_MODEL];
__device__ __nv_bfloat16 g_wq_hi[(size_t)D_MODEL*D_MODEL], g_wq_lo[(size_t)D_MODEL*D_MODEL];
__device__ __nv_bfloat16 g_wk_hi[(size_t)D_MODEL*D_MODEL], g_wk_lo[(size_t)D_MODEL*D_MODEL];
__device__ __nv_bfloat16 g_wv_hi[(size_t)D_MODEL*D_MODEL], g_wv_lo[(size_t)D_MODEL*D_MODEL];
__device__ __nv_bfloat16 g_wo_hi[(size_t)D_MODEL*D_MODEL], g_wo_lo[(size_t)D_MODEL*D_MODEL];
__device__ __nv_bfloat16 g_Qhi[(size_t)MTOT*D_MODEL], g_Qlo[(size_t)MTOT*D_MODEL];
__device__ __nv_bfloat16 g_Khi[(size_t)MTOT*D_MODEL], g_Klo[(size_t)MTOT*D_MODEL];
__device__ __nv_bfloat16 g_Vhi[(size_t)MTOT*D_MODEL], g_Vlo[(size_t)MTOT*D_MODEL];
__device__ __nv_bfloat16 g_Ahi[(size_t)MTOT*D_MODEL], g_Alo[(size_t)MTOT*D_MODEL];
__device__ float g_scl[MTOT];

// ---------------- helpers ----------------
__device__ __forceinline__ uint32_t smem_u32(const void* p) {
    uint32_t a;
    asm("{ .reg .u64 t; cvta.to.shared.u64 t, %1; cvt.u32.u64 %0, t; }" : "=r"(a) : "l"(p));
    return a;
}
__device__ __forceinline__ void ldsm4(uint32_t* r, uint32_t addr) {
    asm volatile("ldmatrix.sync.aligned.m8n8.x4.shared.b16 {%0,%1,%2,%3}, [%4];"
                 : "=r"(r[0]), "=r"(r[1]), "=r"(r[2]), "=r"(r[3]) : "r"(addr));
}
__device__ __forceinline__ void ldsm4t(uint32_t* r, uint32_t addr) {
    asm volatile("ldmatrix.sync.aligned.m8n8.x4.trans.shared.b16 {%0,%1,%2,%3}, [%4];"
                 : "=r"(r[0]), "=r"(r[1]), "=r"(r[2]), "=r"(r[3]) : "r"(addr));
}
__device__ __forceinline__ void mma_bf16(float* d, const uint32_t* a, const uint32_t* b) {
    asm volatile("mma.sync.aligned.m16n8k16.row.col.f32.bf16.bf16.f32 "
                 "{%0,%1,%2,%3}, {%4,%5,%6,%7}, {%8,%9}, {%0,%1,%2,%3};"
                 : "+f"(d[0]), "+f"(d[1]), "+f"(d[2]), "+f"(d[3])
                 : "r"(a[0]), "r"(a[1]), "r"(a[2]), "r"(a[3]), "r"(b[0]), "r"(b[1]));
}
__device__ __forceinline__ void cpa16(uint32_t dst, const void* src) {
    asm volatile("cp.async.cg.shared.global [%0], [%1], 16;" :: "r"(dst), "l"(src));
}
__device__ __forceinline__ void cp_commit() { asm volatile("cp.async.commit_group;"); }
template<int N> __device__ __forceinline__ void cp_wait() {
    asm volatile("cp.async.wait_group %0;" :: "n"(N));
}
__device__ __forceinline__ float ex2(float x) {
    float r;
    asm("ex2.approx.f32 %0, %1;" : "=f"(r) : "f"(x));
    return r;
}
__device__ __forceinline__ uint32_t bits(const __nv_bfloat162& h) {
    return *reinterpret_cast<const uint32_t*>(&h);
}
__device__ __forceinline__ void mk_hilo(uint32_t& hi, uint32_t& lo, float x, float y) {
    __nv_bfloat162 h = __floats2bfloat162_rn(x, y);
    float2 f = __bfloat1622float2(h);
    __nv_bfloat162 l = __floats2bfloat162_rn(x - f.x, y - f.y);
    hi = bits(h); lo = bits(l);
}

// ---------------------------------------------------------------------------
// One-shot conversion of all inputs + per-row scale, single launch.
// ---------------------------------------------------------------------------
__global__ void cvt_all_kernel(
    const float* __restrict__ q, const float* __restrict__ k, const float* __restrict__ v,
    const float* __restrict__ Wq, const float* __restrict__ Wk,
    const float* __restrict__ Wv, const float* __restrict__ Wo,
    const float* __restrict__ phi)
{
    const int bid = blockIdx.x;
    if (bid >= CVT_BLOCKS) {
        const int i = (bid - CVT_BLOCKS) * 256 + threadIdx.x;
        if (i < MTOT) {
            const float* p = phi + (size_t)i * 8;
            float s = 0.f;
#pragma unroll
            for (int f = 0; f < 8; f++) s += p[f];
            g_scl[i] = 1.0f / (8.0f * fmaxf(s * 0.125f, 1e-6f));
        }
        return;
    }
    const int gid = bid * 256 + threadIdx.x;
    const float* src; __nv_bfloat16 *hi, *lo; int idx;
    if (gid < N4A)            { src = q; hi = g_xq_hi; lo = g_xq_lo; idx = gid; }
    else if (gid < 2*N4A)     { src = k; hi = g_xk_hi; lo = g_xk_lo; idx = gid - N4A; }
    else if (gid < 3*N4A)     { src = v; hi = g_xv_hi; lo = g_xv_lo; idx = gid - 2*N4A; }
    else {
        const int w = gid - 3*N4A;
        if (w < N4W)          { src = Wq; hi = g_wq_hi; lo = g_wq_lo; idx = w; }
        else if (w < 2*N4W)   { src = Wk; hi = g_wk_hi; lo = g_wk_lo; idx = w - N4W; }
        else if (w < 3*N4W)   { src = Wv; hi = g_wv_hi; lo = g_wv_lo; idx = w - 2*N4W; }
        else                  { src = Wo; hi = g_wo_hi; lo = g_wo_lo; idx = w - 3*N4W; }
    }
    float4 x = ((const float4*)src)[idx];
    uint32_t h0, l0, h1, l1;
    mk_hilo(h0, l0, x.x, x.y);
    mk_hilo(h1, l1, x.z, x.w);
    ((uint2*)hi)[idx] = make_uint2(h0, h1);
    ((uint2*)lo)[idx] = make_uint2(l0, l1);
}

// ---------------------------------------------------------------------------
// HMMA split-bf16 GEMM body (verified). Caller may invoke repeatedly;
// each call re-primes the cp.async pipeline.
// ---------------------------------------------------------------------------
__device__ __forceinline__ void hmma_gemm_bf16(
    const __nv_bfloat16* __restrict__ Ahi, const __nv_bfloat16* __restrict__ Alo,
    const __nv_bfloat16* __restrict__ Whi, const __nv_bfloat16* __restrict__ Wlo,
    const float* __restrict__ bias,
    float* __restrict__ Cf, __nv_bfloat16* __restrict__ Chi, __nv_bfloat16* __restrict__ Clo)
{
    extern __shared__ char sm[];
    const int tid  = threadIdx.x;
    const int lane = tid & 31;
    const int wid  = tid >> 5;
    const int wm   = wid & 1;
    const int wn   = wid >> 1;
    const int m0   = blockIdx.y * 128;
    const int n0   = blockIdx.x * 128;
    const uint32_t sb = smem_u32(sm);

    float d[4][4][4];
#pragma unroll
    for (int mt = 0; mt < 4; mt++)
#pragma unroll
        for (int nt = 0; nt < 4; nt++)
#pragma unroll
            for (int e = 0; e < 4; e++) d[mt][nt][e] = 0.f;

    const int lrow = tid >> 2;
    const int lch  = tid & 3;
    const uint32_t ldst0 = (uint32_t)(lrow * 64 + ((lch ^ ((lrow >> 1) & 3)) << 4));
    const size_t aoff = (size_t)(m0 + lrow) * D_MODEL + lch * 8;
    const size_t woff = (size_t)(n0 + lrow) * D_MODEL + lch * 8;
    const size_t R64  = (size_t)64 * D_MODEL;

    auto ISSUE = [&](int c) {
        const uint32_t st = sb + (c % 3) * GSTG;
        const int k0 = c * GKC;
        cpa16(st + 0*GOP + ldst0,        Ahi + aoff + k0);
        cpa16(st + 0*GOP + ldst0 + 4096, Ahi + aoff + R64 + k0);
        cpa16(st + 1*GOP + ldst0,        Alo + aoff + k0);
        cpa16(st + 1*GOP + ldst0 + 4096, Alo + aoff + R64 + k0);
        cpa16(st + 2*GOP + ldst0,        Whi + woff + k0);
        cpa16(st + 2*GOP + ldst0 + 4096, Whi + woff + R64 + k0);
        cpa16(st + 3*GOP + ldst0,        Wlo + woff + k0);
        cpa16(st + 3*GOP + ldst0 + 4096, Wlo + woff + R64 + k0);
    };

    const int a_hi = lane >> 4;
    const int b_c  = (lane >> 3) & 1;
    uint32_t a_rb[4], b_rb[2];
    int a_rm[4], b_rm[2];
#pragma unroll
    for (int mt = 0; mt < 4; mt++) {
        int row = wm*64 + mt*16 + (lane & 15);
        a_rb[mt] = row * 64; a_rm[mt] = (row >> 1) & 3;
    }
#pragma unroll
    for (int nh = 0; nh < 2; nh++) {
        int row = wn*32 + nh*16 + (lane & 7) + ((lane >> 4) << 3);
        b_rb[nh] = row * 64; b_rm[nh] = (row >> 1) & 3;
    }

    auto LD_A = [&](uint32_t opbase, int t, uint32_t af[4][4]) {
#pragma unroll
        for (int mt = 0; mt < 4; mt++)
            ldsm4(af[mt], opbase + a_rb[mt] + ((((t<<1)|a_hi) ^ a_rm[mt]) << 4));
    };
    auto LD_B = [&](uint32_t opbase, int t, uint32_t bf[4][2]) {
#pragma unroll
        for (int nh = 0; nh < 2; nh++) {
            uint32_t r[4];
            ldsm4(r, opbase + b_rb[nh] + ((((t<<1)|b_c) ^ b_rm[nh]) << 4));
            bf[nh*2+0][0] = r[0]; bf[nh*2+0][1] = r[1];
            bf[nh*2+1][0] = r[2]; bf[nh*2+1][1] = r[3];
        }
    };
    auto MMA16 = [&](const uint32_t af[4][4], const uint32_t bf[4][2]) {
#pragma unroll
        for (int mt = 0; mt < 4; mt++)
#pragma unroll
            for (int nt = 0; nt < 4; nt++)
                mma_bf16(d[mt][nt], af[mt], bf[nt]);
    };
    auto MMA_CHUNK = [&](int stg) {
        const uint32_t base = sb + stg * GSTG;
        uint32_t af[4][4], bf[4][2];
#pragma unroll
        for (int t = 0; t < 2; t++) {
            LD_A(base + 0*GOP, t, af);
            LD_B(base + 2*GOP, t, bf);
            MMA16(af, bf);
            LD_B(base + 3*GOP, t, bf);
            MMA16(af, bf);
            LD_A(base + 1*GOP, t, af);
            LD_B(base + 2*GOP, t, bf);
            MMA16(af, bf);
        }
    };

    ISSUE(0); cp_commit();
    ISSUE(1); cp_commit();
    for (int c = 0; c < GNCH; c++) {
        cp_wait<1>();
        __syncthreads();
        MMA_CHUNK(c % 3);
        if (c + 2 < GNCH) ISSUE(c + 2);
        cp_commit();
    }

    const int g = lane >> 2, tq = lane & 3;
#pragma unroll
    for (int mt = 0; mt < 4; mt++) {
#pragma unroll
        for (int nt = 0; nt < 4; nt++) {
            const int row = m0 + wm*64 + mt*16 + g;
            const int col = n0 + wn*32 + nt*8 + tq*2;
            const float b0 = bias[col], b1 = bias[col + 1];
            float c0 = d[mt][nt][0] + b0, c1 = d[mt][nt][1] + b1;
            float c2 = d[mt][nt][2] + b0, c3 = d[mt][nt][3] + b1;
            if (Cf) {
                *(float2*)&Cf[(size_t)row * D_MODEL + col]       = make_float2(c0, c1);
                *(float2*)&Cf[(size_t)(row + 8) * D_MODEL + col] = make_float2(c2, c3);
            } else {
                uint32_t h, l;
                mk_hilo(h, l, c0, c1);
                *(uint32_t*)&Chi[(size_t)row * D_MODEL + col] = h;
                *(uint32_t*)&Clo[(size_t)row * D_MODEL + col] = l;
                mk_hilo(h, l, c2, c3);
                *(uint32_t*)&Chi[(size_t)(row + 8) * D_MODEL + col] = h;
                *(uint32_t*)&Clo[(size_t)(row + 8) * D_MODEL + col] = l;
            }
        }
    }
}

// All three projections per CTA: grid 256 (single wave at occ 2), no tail.
__global__ __launch_bounds__(256, 2) void tc_qkv_kernel(
    const float* __restrict__ bq, const float* __restrict__ bk, const float* __restrict__ bv)
{
#pragma unroll 1
    for (int p = 0; p < 3; p++) {
        if (p) __syncthreads();   // prior pass's readers done before re-priming stages
        if (p == 0)
            hmma_gemm_bf16(g_xq_hi, g_xq_lo, g_wq_hi, g_wq_lo, bq, nullptr, g_Qhi, g_Qlo);
        else if (p == 1)
            hmma_gemm_bf16(g_xk_hi, g_xk_lo, g_wk_hi, g_wk_lo, bk, nullptr, g_Khi, g_Klo);
        else
            hmma_gemm_bf16(g_xv_hi, g_xv_lo, g_wv_hi, g_wv_lo, bv, nullptr, g_Vhi, g_Vlo);
    }
}

__global__ __launch_bounds__(256, 2) void tc_out_kernel(
    const float* __restrict__ bo, float* __restrict__ out)
{
    hmma_gemm_bf16(g_Ahi, g_Alo, g_wo_hi, g_wo_lo, bo, out, nullptr, nullptr);
}

// ---------------------------------------------------------------------------
// HMMA flash attention, no-max softmax, 2-stage KV pipeline, occ 2.
// TWO heads per CTA (grid 256 = single wave at occ 2 -> no wave tail).
// ---------------------------------------------------------------------------
__global__ __launch_bounds__(256, 2) void attn_mma_kernel()
{
    extern __shared__ char sm[];
    const int tid  = threadIdx.x;
    const int lane = tid & 31;
    const int wid  = tid >> 5;
    const int b    = blockIdx.z;
    const int q0   = blockIdx.x * 128;
    const uint32_t sb  = smem_u32(sm);
    const uint32_t kvb = sb + 2*AQT;

    // loader mappings (head-independent parts)
    const int qrow = tid >> 3;
    const int qch  = tid & 7;
    const uint32_t qd = (uint32_t)(qrow * 128 + ((qch ^ (qrow & 7)) << 4));
    const int krow = tid >> 3;
    const int kch  = tid & 7;
    const uint32_t kd0 = (uint32_t)(krow * 128 + ((kch ^ (krow & 7)) << 4));
    const size_t R32  = (size_t)32 * D_MODEL;
    const size_t TSTEP = (size_t)64 * D_MODEL;

    // fragment row precompute (head-independent)
    const int g = lane >> 2;
    const int b_c = (lane >> 3) & 1;
    uint32_t k_rb[4]; int k_rm[4];
#pragma unroll
    for (int nq = 0; nq < 4; nq++) {
        int row = nq*16 + (lane & 7) + ((lane >> 4) << 3);
        k_rb[nq] = row * 128; k_rm[nq] = row & 7;
    }
    const int v_hi = lane >> 4;
    uint32_t v_rb[4]; int v_rm[4];
#pragma unroll
    for (int kc = 0; kc < 4; kc++) {
        int row = kc*16 + (lane & 15);
        v_rb[kc] = row * 128; v_rm[kc] = row & 7;
    }

#pragma unroll 1
    for (int hh = 0; hh < 2; hh++) {
        const int h = blockIdx.y * 2 + hh;
        const size_t hoff = (size_t)h * HD;
        // All warps finished reading previous head's KV stages before re-priming
        if (hh) __syncthreads();

        // ---- Q tile cp.async (group) ----
        {
            const size_t qsrc = (size_t)(b*TT + q0 + qrow) * D_MODEL + hoff + qch * 8;
#pragma unroll
            for (int j = 0; j < 4; j++) {
                cpa16(sb + qd + j*4096,       g_Qhi + qsrc + j*R32);
                cpa16(sb + AQT + qd + j*4096, g_Qlo + qsrc + j*R32);
            }
            cp_commit();
        }

        const size_t koff = (size_t)(b*TT + krow) * D_MODEL + hoff + kch * 8;

        auto ISSUEKV = [&](int c) {
            const uint32_t st = kvb + (c & 1) * ASTG;
            const size_t s0 = koff + (size_t)c * TSTEP;
            cpa16(st + 0*AKT + kd0,        g_Khi + s0);
            cpa16(st + 0*AKT + kd0 + 4096, g_Khi + s0 + R32);
            cpa16(st + 1*AKT + kd0,        g_Klo + s0);
            cpa16(st + 1*AKT + kd0 + 4096, g_Klo + s0 + R32);
            cpa16(st + 2*AKT + kd0,        g_Vhi + s0);
            cpa16(st + 2*AKT + kd0 + 4096, g_Vhi + s0 + R32);
            cpa16(st + 3*AKT + kd0,        g_Vlo + s0);
            cpa16(st + 3*AKT + kd0 + 4096, g_Vlo + s0 + R32);
        };

        ISSUEKV(0); cp_commit();
        ISSUEKV(1); cp_commit();

        // Q + KV0 ready (only KV1 may remain outstanding)
        cp_wait<1>();
        __syncthreads();

        uint32_t qh[4][4], ql[4][4];
        {
            const int qr  = wid*16 + (lane & 15);
            const uint32_t qrb = (uint32_t)qr * 128;
            const int qrm = qr & 7;
            const int qhi = lane >> 4;
#pragma unroll
            for (int kc = 0; kc < 4; kc++) {
                ldsm4(qh[kc], sb       + qrb + ((((kc<<1)|qhi) ^ qrm) << 4));
                ldsm4(ql[kc], sb + AQT + qrb + ((((kc<<1)|qhi) ^ qrm) << 4));
            }
        }

        const float rs2_0 = g_scl[b*TT + q0 + wid*16 + g]     * 1.4426950408889634f;
        const float rs2_1 = g_scl[b*TT + q0 + wid*16 + g + 8] * 1.4426950408889634f;
        float l0 = 0.f, l1 = 0.f;
        float o[8][4];
#pragma unroll
        for (int dn = 0; dn < 8; dn++)
#pragma unroll
            for (int e = 0; e < 4; e++) o[dn][e] = 0.f;

        auto COMPUTE = [&](int stg) {
            const uint32_t kh = kvb + stg * ASTG;
            const uint32_t kl = kh + AKT;
            const uint32_t vh = kh + 2*AKT;
            const uint32_t vl = kh + 3*AKT;

            float s[8][4];
#pragma unroll
            for (int nt = 0; nt < 8; nt++)
#pragma unroll
                for (int e = 0; e < 4; e++) s[nt][e] = 0.f;

#pragma unroll
            for (int kc = 0; kc < 4; kc++) {
#pragma unroll
                for (int nq = 0; nq < 4; nq++) {
                    const uint32_t co = ((((kc<<1)|b_c) ^ k_rm[nq]) << 4);
                    uint32_t r[4];
                    ldsm4(r, kh + k_rb[nq] + co);
                    uint32_t b0[2] = { r[0], r[1] }, b1[2] = { r[2], r[3] };
                    mma_bf16(s[2*nq],   qh[kc], b0);
                    mma_bf16(s[2*nq+1], qh[kc], b1);
                    mma_bf16(s[2*nq],   ql[kc], b0);
                    mma_bf16(s[2*nq+1], ql[kc], b1);
                    ldsm4(r, kl + k_rb[nq] + co);
                    uint32_t c0[2] = { r[0], r[1] }, c1[2] = { r[2], r[3] };
                    mma_bf16(s[2*nq],   qh[kc], c0);
                    mma_bf16(s[2*nq+1], qh[kc], c1);
                }
            }

            // no-max softmax
#pragma unroll
            for (int nt = 0; nt < 8; nt++) {
                s[nt][0] = ex2(s[nt][0] * rs2_0);
                s[nt][1] = ex2(s[nt][1] * rs2_0);
                s[nt][2] = ex2(s[nt][2] * rs2_1);
                s[nt][3] = ex2(s[nt][3] * rs2_1);
                l0 += s[nt][0] + s[nt][1];
                l1 += s[nt][2] + s[nt][3];
            }

            // O += P V
#pragma unroll
            for (int kc = 0; kc < 4; kc++) {
                uint32_t ah[4], al[4];
                mk_hilo(ah[0], al[0], s[2*kc][0],   s[2*kc][1]);
                mk_hilo(ah[1], al[1], s[2*kc][2],   s[2*kc][3]);
                mk_hilo(ah[2], al[2], s[2*kc+1][0], s[2*kc+1][1]);
                mk_hilo(ah[3], al[3], s[2*kc+1][2], s[2*kc+1][3]);
#pragma unroll
                for (int dq = 0; dq < 4; dq++) {
                    const uint32_t co = ((((dq<<1)|v_hi) ^ v_rm[kc]) << 4);
                    uint32_t r[4];
                    ldsm4t(r, vh + v_rb[kc] + co);
                    uint32_t b0[2] = { r[0], r[1] }, b1[2] = { r[2], r[3] };
                    mma_bf16(o[2*dq],   ah, b0);
                    mma_bf16(o[2*dq+1], ah, b1);
                    mma_bf16(o[2*dq],   al, b0);
                    mma_bf16(o[2*dq+1], al, b1);
                    ldsm4t(r, vl + v_rb[kc] + co);
                    uint32_t c0[2] = { r[0], r[1] }, c1[2] = { r[2], r[3] };
                    mma_bf16(o[2*dq],   ah, c0);
                    mma_bf16(o[2*dq+1], ah, c1);
                }
            }
        };

        for (int c = 0; c < NKT; c++) {
            cp_wait<1>();
            __syncthreads();
            COMPUTE(c & 1);
            __syncthreads();
            if (c + 2 < NKT) { ISSUEKV(c + 2); }
            cp_commit();
        }

        l0 += __shfl_xor_sync(0xffffffffu, l0, 1);
        l0 += __shfl_xor_sync(0xffffffffu, l0, 2);
        l1 += __shfl_xor_sync(0xffffffffu, l1, 1);
        l1 += __shfl_xor_sync(0xffffffffu, l1, 2);

        const float inv0 = 1.0f / l0, inv1 = 1.0f / l1;
        const int t2 = (lane & 3) * 2;
        const size_t row0 = (size_t)(b*TT + q0 + wid*16 + g);
#pragma unroll
        for (int dn = 0; dn < 8; dn++) {
            uint32_t hb, lb;
            mk_hilo(hb, lb, o[dn][0]*inv0, o[dn][1]*inv0);
            *(uint32_t*)&g_Ahi[row0 * D_MODEL + hoff + dn*8 + t2] = hb;
            *(uint32_t*)&g_Alo[row0 * D_MODEL + hoff + dn*8 + t2] = lb;
            mk_hilo(hb, lb, o[dn][2]*inv1, o[dn][3]*inv1);
            *(uint32_t*)&g_Ahi[(row0 + 8) * D_MODEL + hoff + dn*8 + t2] = hb;
            *(uint32_t*)&g_Alo[(row0 + 8) * D_MODEL + hoff + dn*8 + t2] = lb;
        }
    }
}

// ---------------------------------------------------------------------------
extern "C" void kernel_launch(void* const* d_in, const int* in_sizes, int n_in,
                              void* d_out, int out_size)
{
    const float* query = (const float*)d_in[0];
    const float* key   = (const float*)d_in[1];
    const float* value = (const float*)d_in[2];
    const float* phi   = (const float*)d_in[3];
    // d_in[4] logvar, d_in[13] w_sigma, d_in[14] w_phi: cancel under softmax
    const float* Wq = (const float*)d_in[5];
    const float* bq = (const float*)d_in[6];
    const float* Wk = (const float*)d_in[7];
    const float* bk = (const float*)d_in[8];
    const float* Wv = (const float*)d_in[9];
    const float* bv = (const float*)d_in[10];
    const float* Wo = (const float*)d_in[11];
    const float* bo = (const float*)d_in[12];
    float* out = (float*)d_out;

    cudaFuncSetAttribute(tc_qkv_kernel,   cudaFuncAttributeMaxDynamicSharedMemorySize, GEMM_SMEM);
    cudaFuncSetAttribute(tc_out_kernel,   cudaFuncAttributeMaxDynamicSharedMemorySize, GEMM_SMEM);
    cudaFuncSetAttribute(attn_mma_kernel, cudaFuncAttributeMaxDynamicSharedMemorySize, ATTN_SMEM);

    cvt_all_kernel<<<CVT_BLOCKS + SCL_BLOCKS, 256>>>(query, key, value, Wq, Wk, Wv, Wo, phi);
    tc_qkv_kernel<<<dim3(D_MODEL/128, MTOT/128, 1), 256, GEMM_SMEM>>>(bq, bk, bv);
    attn_mma_kernel<<<dim3(TT/128, HEADS/2, BB), 256, ATTN_SMEM>>>();
    tc_out_kernel<<<dim3(D_MODEL/128, MTOT/128, 1), 256, GEMM_SMEM>>>(bo, out);
}

// round 14
// speedup vs baseline: 1.0395x; 1.0395x over previous
#include <cuda_runtime.h>
#include <cuda_bf16.h>
#include <cstdint>

#define D_MODEL 1024
#define HEADS   16
#define HD      64
#define BB      2
#define TT      2048
#define MTOT    (BB*TT)

// ---------------- GEMM config ----------------
#define GKC   32
#define GNCH  (D_MODEL/GKC)
#define GOP   8192
#define GSTG  (4*GOP)
#define GEMM_SMEM (3*GSTG)

// ---------------- attention config (3-stage via Q-region reuse, occ 2) ----
#define AQT   16384
#define AKT   8192
#define ASTG  (4*AKT)                 // 32768 == 2*AQT (Q region reused as stage 2)
#define ATTN_SMEM (2*AQT + 2*ASTG)    // 98304
#define NKT   (TT/64)

// ---------------- cvt config ----------------
#define N4A (MTOT*D_MODEL/4)
#define N4W (D_MODEL*D_MODEL/4)
#define CVT_BLOCKS ((3*N4A + 4*N4W)/256)
#define SCL_BLOCKS (MTOT/256)

// -------- scratch (device globals; allocations forbidden) --------
__device__ __nv_bfloat16 g_xq_hi[(size_t)MTOT*D_MODEL], g_xq_lo[(size_t)MTOT*D_MODEL];
__device__ __nv_bfloat16 g_xk_hi[(size_t)MTOT*D_MODEL], g_xk_lo[(size_t)MTOT*D_MODEL];
__device__ __nv_bfloat16 g_xv_hi[(size_t)MTOT*D_MODEL], g_xv_lo[(size_t)MTOT*D_MODEL];
__device__ __nv_bfloat16 g_wq_hi[(size_t)D_MODEL*D_MODEL], g_wq_lo[(size_t)D_MODEL*D_MODEL];
__device__ __nv_bfloat16 g_wk_hi[(size_t)D_MODEL*D_MODEL], g_wk_lo[(size_t)D_MODEL*D_MODEL];
__device__ __nv_bfloat16 g_wv_hi[(size_t)D_MODEL*D_MODEL], g_wv_lo[(size_t)D_MODEL*D_MODEL];
__device__ __nv_bfloat16 g_wo_hi[(size_t)D_MODEL*D_MODEL], g_wo_lo[(size_t)D_MODEL*D_MODEL];
__device__ __nv_bfloat16 g_Qhi[(size_t)MTOT*D_MODEL], g_Qlo[(size_t)MTOT*D_MODEL];
__device__ __nv_bfloat16 g_Khi[(size_t)MTOT*D_MODEL], g_Klo[(size_t)MTOT*D_MODEL];
__device__ __nv_bfloat16 g_Vhi[(size_t)MTOT*D_MODEL], g_Vlo[(size_t)MTOT*D_MODEL];
__device__ __nv_bfloat16 g_Ahi[(size_t)MTOT*D_MODEL], g_Alo[(size_t)MTOT*D_MODEL];
__device__ float g_scl[MTOT];

// ---------------- helpers ----------------
__device__ __forceinline__ uint32_t smem_u32(const void* p) {
    uint32_t a;
    asm("{ .reg .u64 t; cvta.to.shared.u64 t, %1; cvt.u32.u64 %0, t; }" : "=r"(a) : "l"(p));
    return a;
}
__device__ __forceinline__ void ldsm4(uint32_t* r, uint32_t addr) {
    asm volatile("ldmatrix.sync.aligned.m8n8.x4.shared.b16 {%0,%1,%2,%3}, [%4];"
                 : "=r"(r[0]), "=r"(r[1]), "=r"(r[2]), "=r"(r[3]) : "r"(addr));
}
__device__ __forceinline__ void ldsm4t(uint32_t* r, uint32_t addr) {
    asm volatile("ldmatrix.sync.aligned.m8n8.x4.trans.shared.b16 {%0,%1,%2,%3}, [%4];"
                 : "=r"(r[0]), "=r"(r[1]), "=r"(r[2]), "=r"(r[3]) : "r"(addr));
}
__device__ __forceinline__ void mma_bf16(float* d, const uint32_t* a, const uint32_t* b) {
    asm volatile("mma.sync.aligned.m16n8k16.row.col.f32.bf16.bf16.f32 "
                 "{%0,%1,%2,%3}, {%4,%5,%6,%7}, {%8,%9}, {%0,%1,%2,%3};"
                 : "+f"(d[0]), "+f"(d[1]), "+f"(d[2]), "+f"(d[3])
                 : "r"(a[0]), "r"(a[1]), "r"(a[2]), "r"(a[3]), "r"(b[0]), "r"(b[1]));
}
__device__ __forceinline__ void cpa16(uint32_t dst, const void* src) {
    asm volatile("cp.async.cg.shared.global [%0], [%1], 16;" :: "r"(dst), "l"(src));
}
__device__ __forceinline__ void cp_commit() { asm volatile("cp.async.commit_group;"); }
template<int N> __device__ __forceinline__ void cp_wait() {
    asm volatile("cp.async.wait_group %0;" :: "n"(N));
}
__device__ __forceinline__ float ex2(float x) {
    float r;
    asm("ex2.approx.f32 %0, %1;" : "=f"(r) : "f"(x));
    return r;
}
__device__ __forceinline__ uint32_t bits(const __nv_bfloat162& h) {
    return *reinterpret_cast<const uint32_t*>(&h);
}
__device__ __forceinline__ void mk_hilo(uint32_t& hi, uint32_t& lo, float x, float y) {
    __nv_bfloat162 h = __floats2bfloat162_rn(x, y);
    float2 f = __bfloat1622float2(h);
    __nv_bfloat162 l = __floats2bfloat162_rn(x - f.x, y - f.y);
    hi = bits(h); lo = bits(l);
}

// ---------------------------------------------------------------------------
// One-shot conversion of all inputs + per-row scale, single launch.
// ---------------------------------------------------------------------------
__global__ void cvt_all_kernel(
    const float* __restrict__ q, const float* __restrict__ k, const float* __restrict__ v,
    const float* __restrict__ Wq, const float* __restrict__ Wk,
    const float* __restrict__ Wv, const float* __restrict__ Wo,
    const float* __restrict__ phi)
{
    const int bid = blockIdx.x;
    if (bid >= CVT_BLOCKS) {
        const int i = (bid - CVT_BLOCKS) * 256 + threadIdx.x;
        if (i < MTOT) {
            const float* p = phi + (size_t)i * 8;
            float s = 0.f;
#pragma unroll
            for (int f = 0; f < 8; f++) s += p[f];
            g_scl[i] = 1.0f / (8.0f * fmaxf(s * 0.125f, 1e-6f));
        }
        return;
    }
    const int gid = bid * 256 + threadIdx.x;
    const float* src; __nv_bfloat16 *hi, *lo; int idx;
    if (gid < N4A)            { src = q; hi = g_xq_hi; lo = g_xq_lo; idx = gid; }
    else if (gid < 2*N4A)     { src = k; hi = g_xk_hi; lo = g_xk_lo; idx = gid - N4A; }
    else if (gid < 3*N4A)     { src = v; hi = g_xv_hi; lo = g_xv_lo; idx = gid - 2*N4A; }
    else {
        const int w = gid - 3*N4A;
        if (w < N4W)          { src = Wq; hi = g_wq_hi; lo = g_wq_lo; idx = w; }
        else if (w < 2*N4W)   { src = Wk; hi = g_wk_hi; lo = g_wk_lo; idx = w - N4W; }
        else if (w < 3*N4W)   { src = Wv; hi = g_wv_hi; lo = g_wv_lo; idx = w - 2*N4W; }
        else                  { src = Wo; hi = g_wo_hi; lo = g_wo_lo; idx = w - 3*N4W; }
    }
    float4 x = ((const float4*)src)[idx];
    uint32_t h0, l0, h1, l1;
    mk_hilo(h0, l0, x.x, x.y);
    mk_hilo(h1, l1, x.z, x.w);
    ((uint2*)hi)[idx] = make_uint2(h0, h1);
    ((uint2*)lo)[idx] = make_uint2(l0, l1);
}

// ---------------------------------------------------------------------------
// HMMA split-bf16 GEMM (unchanged — verified, 61% tensor)
// ---------------------------------------------------------------------------
__device__ __forceinline__ void hmma_gemm_bf16(
    const __nv_bfloat16* __restrict__ Ahi, const __nv_bfloat16* __restrict__ Alo,
    const __nv_bfloat16* __restrict__ Whi, const __nv_bfloat16* __restrict__ Wlo,
    const float* __restrict__ bias,
    float* __restrict__ Cf, __nv_bfloat16* __restrict__ Chi, __nv_bfloat16* __restrict__ Clo)
{
    extern __shared__ char sm[];
    const int tid  = threadIdx.x;
    const int lane = tid & 31;
    const int wid  = tid >> 5;
    const int wm   = wid & 1;
    const int wn   = wid >> 1;
    const int m0   = blockIdx.y * 128;
    const int n0   = blockIdx.x * 128;
    const uint32_t sb = smem_u32(sm);

    float d[4][4][4];
#pragma unroll
    for (int mt = 0; mt < 4; mt++)
#pragma unroll
        for (int nt = 0; nt < 4; nt++)
#pragma unroll
            for (int e = 0; e < 4; e++) d[mt][nt][e] = 0.f;

    const int lrow = tid >> 2;
    const int lch  = tid & 3;
    const uint32_t ldst0 = (uint32_t)(lrow * 64 + ((lch ^ ((lrow >> 1) & 3)) << 4));
    const size_t aoff = (size_t)(m0 + lrow) * D_MODEL + lch * 8;
    const size_t woff = (size_t)(n0 + lrow) * D_MODEL + lch * 8;
    const size_t R64  = (size_t)64 * D_MODEL;

    auto ISSUE = [&](int c) {
        const uint32_t st = sb + (c % 3) * GSTG;
        const int k0 = c * GKC;
        cpa16(st + 0*GOP + ldst0,        Ahi + aoff + k0);
        cpa16(st + 0*GOP + ldst0 + 4096, Ahi + aoff + R64 + k0);
        cpa16(st + 1*GOP + ldst0,        Alo + aoff + k0);
        cpa16(st + 1*GOP + ldst0 + 4096, Alo + aoff + R64 + k0);
        cpa16(st + 2*GOP + ldst0,        Whi + woff + k0);
        cpa16(st + 2*GOP + ldst0 + 4096, Whi + woff + R64 + k0);
        cpa16(st + 3*GOP + ldst0,        Wlo + woff + k0);
        cpa16(st + 3*GOP + ldst0 + 4096, Wlo + woff + R64 + k0);
    };

    const int a_hi = lane >> 4;
    const int b_c  = (lane >> 3) & 1;
    uint32_t a_rb[4], b_rb[2];
    int a_rm[4], b_rm[2];
#pragma unroll
    for (int mt = 0; mt < 4; mt++) {
        int row = wm*64 + mt*16 + (lane & 15);
        a_rb[mt] = row * 64; a_rm[mt] = (row >> 1) & 3;
    }
#pragma unroll
    for (int nh = 0; nh < 2; nh++) {
        int row = wn*32 + nh*16 + (lane & 7) + ((lane >> 4) << 3);
        b_rb[nh] = row * 64; b_rm[nh] = (row >> 1) & 3;
    }

    auto LD_A = [&](uint32_t opbase, int t, uint32_t af[4][4]) {
#pragma unroll
        for (int mt = 0; mt < 4; mt++)
            ldsm4(af[mt], opbase + a_rb[mt] + ((((t<<1)|a_hi) ^ a_rm[mt]) << 4));
    };
    auto LD_B = [&](uint32_t opbase, int t, uint32_t bf[4][2]) {
#pragma unroll
        for (int nh = 0; nh < 2; nh++) {
            uint32_t r[4];
            ldsm4(r, opbase + b_rb[nh] + ((((t<<1)|b_c) ^ b_rm[nh]) << 4));
            bf[nh*2+0][0] = r[0]; bf[nh*2+0][1] = r[1];
            bf[nh*2+1][0] = r[2]; bf[nh*2+1][1] = r[3];
        }
    };
    auto MMA16 = [&](const uint32_t af[4][4], const uint32_t bf[4][2]) {
#pragma unroll
        for (int mt = 0; mt < 4; mt++)
#pragma unroll
            for (int nt = 0; nt < 4; nt++)
                mma_bf16(d[mt][nt], af[mt], bf[nt]);
    };
    auto MMA_CHUNK = [&](int stg) {
        const uint32_t base = sb + stg * GSTG;
        uint32_t af[4][4], bf[4][2];
#pragma unroll
        for (int t = 0; t < 2; t++) {
            LD_A(base + 0*GOP, t, af);
            LD_B(base + 2*GOP, t, bf);
            MMA16(af, bf);
            LD_B(base + 3*GOP, t, bf);
            MMA16(af, bf);
            LD_A(base + 1*GOP, t, af);
            LD_B(base + 2*GOP, t, bf);
            MMA16(af, bf);
        }
    };

    ISSUE(0); cp_commit();
    ISSUE(1); cp_commit();
    for (int c = 0; c < GNCH; c++) {
        cp_wait<1>();
        __syncthreads();
        MMA_CHUNK(c % 3);
        if (c + 2 < GNCH) ISSUE(c + 2);
        cp_commit();
    }

    const int g = lane >> 2, tq = lane & 3;
#pragma unroll
    for (int mt = 0; mt < 4; mt++) {
#pragma unroll
        for (int nt = 0; nt < 4; nt++) {
            const int row = m0 + wm*64 + mt*16 + g;
            const int col = n0 + wn*32 + nt*8 + tq*2;
            const float b0 = bias[col], b1 = bias[col + 1];
            float c0 = d[mt][nt][0] + b0, c1 = d[mt][nt][1] + b1;
            float c2 = d[mt][nt][2] + b0, c3 = d[mt][nt][3] + b1;
            if (Cf) {
                *(float2*)&Cf[(size_t)row * D_MODEL + col]       = make_float2(c0, c1);
                *(float2*)&Cf[(size_t)(row + 8) * D_MODEL + col] = make_float2(c2, c3);
            } else {
                uint32_t h, l;
                mk_hilo(h, l, c0, c1);
                *(uint32_t*)&Chi[(size_t)row * D_MODEL + col] = h;
                *(uint32_t*)&Clo[(size_t)row * D_MODEL + col] = l;
                mk_hilo(h, l, c2, c3);
                *(uint32_t*)&Chi[(size_t)(row + 8) * D_MODEL + col] = h;
                *(uint32_t*)&Clo[(size_t)(row + 8) * D_MODEL + col] = l;
            }
        }
    }
}

__global__ __launch_bounds__(256, 2) void tc_qkv_kernel(
    const float* __restrict__ bq, const float* __restrict__ bk, const float* __restrict__ bv)
{
    if (blockIdx.z == 0)
        hmma_gemm_bf16(g_xq_hi, g_xq_lo, g_wq_hi, g_wq_lo, bq, nullptr, g_Qhi, g_Qlo);
    else if (blockIdx.z == 1)
        hmma_gemm_bf16(g_xk_hi, g_xk_lo, g_wk_hi, g_wk_lo, bk, nullptr, g_Khi, g_Klo);
    else
        hmma_gemm_bf16(g_xv_hi, g_xv_lo, g_wv_hi, g_wv_lo, bv, nullptr, g_Vhi, g_Vlo);
}

__global__ __launch_bounds__(256, 2) void tc_out_kernel(
    const float* __restrict__ bo, float* __restrict__ out)
{
    hmma_gemm_bf16(g_Ahi, g_Alo, g_wo_hi, g_wo_lo, bo, out, nullptr, nullptr);
}

// ---------------------------------------------------------------------------
// HMMA flash attention, no-max softmax, occ 2.
// 3-stage KV pipeline in 2-stage footprint: after Q fragments are hoisted to
// registers, the Q smem region (2*AQT == ASTG bytes) becomes KV stage 2.
// Single __syncthreads per tile (GEMM-pattern pipeline).
// ---------------------------------------------------------------------------
__global__ __launch_bounds__(256, 2) void attn_mma_kernel()
{
    extern __shared__ char sm[];
    const int tid  = threadIdx.x;
    const int lane = tid & 31;
    const int wid  = tid >> 5;
    const int b    = blockIdx.z, h = blockIdx.y;
    const int q0   = blockIdx.x * 128;
    const uint32_t sb  = smem_u32(sm);
    const uint32_t kvb = sb + 2*AQT;
    const size_t hoff = (size_t)h * HD;

    // KV stage address: stages 0,1 after Q region; stage 2 reuses Q region.
    auto STADDR = [&](int s) -> uint32_t {
        return (s == 2) ? sb : kvb + (uint32_t)s * ASTG;
    };

    // ---- Q tile cp.async (group 0) ----
    {
        const int qrow = tid >> 3;
        const int qch  = tid & 7;
        const uint32_t qd = (uint32_t)(qrow * 128 + ((qch ^ (qrow & 7)) << 4));
        const size_t qsrc = (size_t)(b*TT + q0 + qrow) * D_MODEL + hoff + qch * 8;
        const size_t R32 = (size_t)32 * D_MODEL;
#pragma unroll
        for (int j = 0; j < 4; j++) {
            cpa16(sb + qd + j*4096,       g_Qhi + qsrc + j*R32);
            cpa16(sb + AQT + qd + j*4096, g_Qlo + qsrc + j*R32);
        }
        cp_commit();
    }

    const int krow = tid >> 3;
    const int kch  = tid & 7;
    const uint32_t kd0 = (uint32_t)(krow * 128 + ((kch ^ (krow & 7)) << 4));
    const size_t koff = (size_t)(b*TT + krow) * D_MODEL + hoff + kch * 8;
    const size_t R32  = (size_t)32 * D_MODEL;
    const size_t TSTEP = (size_t)64 * D_MODEL;

    auto ISSUEKV = [&](int c) {
        const uint32_t st = STADDR(c % 3);
        const size_t s0 = koff + (size_t)c * TSTEP;
        cpa16(st + 0*AKT + kd0,        g_Khi + s0);
        cpa16(st + 0*AKT + kd0 + 4096, g_Khi + s0 + R32);
        cpa16(st + 1*AKT + kd0,        g_Klo + s0);
        cpa16(st + 1*AKT + kd0 + 4096, g_Klo + s0 + R32);
        cpa16(st + 2*AKT + kd0,        g_Vhi + s0);
        cpa16(st + 2*AKT + kd0 + 4096, g_Vhi + s0 + R32);
        cpa16(st + 3*AKT + kd0,        g_Vlo + s0);
        cpa16(st + 3*AKT + kd0 + 4096, g_Vlo + s0 + R32);
    };

    ISSUEKV(0); cp_commit();   // group 1 (stage 0)
    ISSUEKV(1); cp_commit();   // group 2 (stage 1)

    // ---- Q landed (pending <= 2 leaves KV0,KV1 outstanding; Q done) ----
    cp_wait<2>();
    __syncthreads();

    uint32_t qh[4][4], ql[4][4];
    {
        const int qr  = wid*16 + (lane & 15);
        const uint32_t qrb = (uint32_t)qr * 128;
        const int qrm = qr & 7;
        const int qhi = lane >> 4;
#pragma unroll
        for (int kc = 0; kc < 4; kc++) {
            ldsm4(qh[kc], sb       + qrb + ((((kc<<1)|qhi) ^ qrm) << 4));
            ldsm4(ql[kc], sb + AQT + qrb + ((((kc<<1)|qhi) ^ qrm) << 4));
        }
    }
    // NOTE: stage 2 (Q region) is first overwritten by ISSUEKV(2), issued
    // AFTER the c=0 barrier below — all warps have consumed Q frags by then.

    const int g = lane >> 2;
    const float rs2_0 = g_scl[b*TT + q0 + wid*16 + g]     * 1.4426950408889634f;
    const float rs2_1 = g_scl[b*TT + q0 + wid*16 + g + 8] * 1.4426950408889634f;
    float l0 = 0.f, l1 = 0.f;
    float o[8][4];
#pragma unroll
    for (int dn = 0; dn < 8; dn++)
#pragma unroll
        for (int e = 0; e < 4; e++) o[dn][e] = 0.f;

    const int b_c = (lane >> 3) & 1;
    uint32_t k_rb[4]; int k_rm[4];
#pragma unroll
    for (int nq = 0; nq < 4; nq++) {
        int row = nq*16 + (lane & 7) + ((lane >> 4) << 3);
        k_rb[nq] = row * 128; k_rm[nq] = row & 7;
    }
    const int v_hi = lane >> 4;
    uint32_t v_rb[4]; int v_rm[4];
#pragma unroll
    for (int kc = 0; kc < 4; kc++) {
        int row = kc*16 + (lane & 15);
        v_rb[kc] = row * 128; v_rm[kc] = row & 7;
    }

    auto COMPUTE = [&](uint32_t kh) {
        const uint32_t kl = kh + AKT;
        const uint32_t vh = kh + 2*AKT;
        const uint32_t vl = kh + 3*AKT;

        // ---- S = Q K^T (3-MMA split) ----
        float s[8][4];
#pragma unroll
        for (int nt = 0; nt < 8; nt++)
#pragma unroll
            for (int e = 0; e < 4; e++) s[nt][e] = 0.f;

#pragma unroll
        for (int kc = 0; kc < 4; kc++) {
#pragma unroll
            for (int nq = 0; nq < 4; nq++) {
                const uint32_t co = ((((kc<<1)|b_c) ^ k_rm[nq]) << 4);
                uint32_t r[4];
                ldsm4(r, kh + k_rb[nq] + co);
                uint32_t b0[2] = { r[0], r[1] }, b1[2] = { r[2], r[3] };
                mma_bf16(s[2*nq],   qh[kc], b0);
                mma_bf16(s[2*nq+1], qh[kc], b1);
                mma_bf16(s[2*nq],   ql[kc], b0);
                mma_bf16(s[2*nq+1], ql[kc], b1);
                ldsm4(r, kl + k_rb[nq] + co);
                uint32_t c0[2] = { r[0], r[1] }, c1[2] = { r[2], r[3] };
                mma_bf16(s[2*nq],   qh[kc], c0);
                mma_bf16(s[2*nq+1], qh[kc], c1);
            }
        }

        // ---- no-max softmax: p = 2^(s*rs*log2e); per-thread row sums ----
#pragma unroll
        for (int nt = 0; nt < 8; nt++) {
            s[nt][0] = ex2(s[nt][0] * rs2_0);
            s[nt][1] = ex2(s[nt][1] * rs2_0);
            s[nt][2] = ex2(s[nt][2] * rs2_1);
            s[nt][3] = ex2(s[nt][3] * rs2_1);
            l0 += s[nt][0] + s[nt][1];
            l1 += s[nt][2] + s[nt][3];
        }

        // ---- O += P V (3-MMA split), V via trans ldmatrix ----
#pragma unroll
        for (int kc = 0; kc < 4; kc++) {
            uint32_t ah[4], al[4];
            mk_hilo(ah[0], al[0], s[2*kc][0],   s[2*kc][1]);
            mk_hilo(ah[1], al[1], s[2*kc][2],   s[2*kc][3]);
            mk_hilo(ah[2], al[2], s[2*kc+1][0], s[2*kc+1][1]);
            mk_hilo(ah[3], al[3], s[2*kc+1][2], s[2*kc+1][3]);
#pragma unroll
            for (int dq = 0; dq < 4; dq++) {
                const uint32_t co = ((((dq<<1)|v_hi) ^ v_rm[kc]) << 4);
                uint32_t r[4];
                ldsm4t(r, vh + v_rb[kc] + co);
                uint32_t b0[2] = { r[0], r[1] }, b1[2] = { r[2], r[3] };
                mma_bf16(o[2*dq],   ah, b0);
                mma_bf16(o[2*dq+1], ah, b1);
                mma_bf16(o[2*dq],   al, b0);
                mma_bf16(o[2*dq+1], al, b1);
                ldsm4t(r, vl + v_rb[kc] + co);
                uint32_t c0[2] = { r[0], r[1] }, c1[2] = { r[2], r[3] };
                mma_bf16(o[2*dq],   ah, c0);
                mma_bf16(o[2*dq+1], ah, c1);
            }
        }
    };

    // ---- main loop: 3-stage, ONE sync per tile (GEMM pattern) ----
    for (int c = 0; c < NKT; c++) {
        cp_wait<1>();          // KV(c) resident (KV(c+1) may still be in flight)
        __syncthreads();       // all warps past reads of stage (c-1)%3
        COMPUTE(STADDR(c % 3));
        if (c + 2 < NKT) ISSUEKV(c + 2);   // writes stage (c+2)%3 == (c-1)%3
        cp_commit();
    }

    // ---- single end-of-loop row-sum reduction ----
    l0 += __shfl_xor_sync(0xffffffffu, l0, 1);
    l0 += __shfl_xor_sync(0xffffffffu, l0, 2);
    l1 += __shfl_xor_sync(0xffffffffu, l1, 1);
    l1 += __shfl_xor_sync(0xffffffffu, l1, 2);

    // ---- normalize & write split-bf16 head output ----
    const float inv0 = 1.0f / l0, inv1 = 1.0f / l1;
    const int t2 = (lane & 3) * 2;
    const size_t row0 = (size_t)(b*TT + q0 + wid*16 + g);
#pragma unroll
    for (int dn = 0; dn < 8; dn++) {
        uint32_t hb, lb;
        mk_hilo(hb, lb, o[dn][0]*inv0, o[dn][1]*inv0);
        *(uint32_t*)&g_Ahi[row0 * D_MODEL + hoff + dn*8 + t2] = hb;
        *(uint32_t*)&g_Alo[row0 * D_MODEL + hoff + dn*8 + t2] = lb;
        mk_hilo(hb, lb, o[dn][2]*inv1, o[dn][3]*inv1);
        *(uint32_t*)&g_Ahi[(row0 + 8) * D_MODEL + hoff + dn*8 + t2] = hb;
        *(uint32_t*)&g_Alo[(row0 + 8) * D_MODEL + hoff + dn*8 + t2] = lb;
    }
}

// ---------------------------------------------------------------------------
extern "C" void kernel_launch(void* const* d_in, const int* in_sizes, int n_in,
                              void* d_out, int out_size)
{
    const float* query = (const float*)d_in[0];
    const float* key   = (const float*)d_in[1];
    const float* value = (const float*)d_in[2];
    const float* phi   = (const float*)d_in[3];
    // d_in[4] logvar, d_in[13] w_sigma, d_in[14] w_phi: cancel under softmax
    const float* Wq = (const float*)d_in[5];
    const float* bq = (const float*)d_in[6];
    const float* Wk = (const float*)d_in[7];
    const float* bk = (const float*)d_in[8];
    const float* Wv = (const float*)d_in[9];
    const float* bv = (const float*)d_in[10];
    const float* Wo = (const float*)d_in[11];
    const float* bo = (const float*)d_in[12];
    float* out = (float*)d_out;

    cudaFuncSetAttribute(tc_qkv_kernel,   cudaFuncAttributeMaxDynamicSharedMemorySize, GEMM_SMEM);
    cudaFuncSetAttribute(tc_out_kernel,   cudaFuncAttributeMaxDynamicSharedMemorySize, GEMM_SMEM);
    cudaFuncSetAttribute(attn_mma_kernel, cudaFuncAttributeMaxDynamicSharedMemorySize, ATTN_SMEM);

    cvt_all_kernel<<<CVT_BLOCKS + SCL_BLOCKS, 256>>>(query, key, value, Wq, Wk, Wv, Wo, phi);
    tc_qkv_kernel<<<dim3(D_MODEL/128, MTOT/128, 3), 256, GEMM_SMEM>>>(bq, bk, bv);
    attn_mma_kernel<<<dim3(TT/128, HEADS, BB), 256, ATTN_SMEM>>>();
    tc_out_kernel<<<dim3(D_MODEL/128, MTOT/128, 1), 256, GEMM_SMEM>>>(bo, out);
}

// round 15
// speedup vs baseline: 1.0472x; 1.0074x over previous
#include <cuda_runtime.h>
#include <cuda_bf16.h>
#include <cstdint>

#define D_MODEL 1024
#define HEADS   16
#define HD      64
#define BB      2
#define TT      2048
#define MTOT    (BB*TT)
#define LOG2E   1.4426950408889634f

// ---------------- GEMM config ----------------
#define GKC   32
#define GNCH  (D_MODEL/GKC)
#define GOP   8192
#define GSTG  (4*GOP)
#define GEMM_SMEM (3*GSTG)

// ---------------- attention config (3-stage via Q-region reuse, occ 2) ----
#define AQT   16384
#define AKT   8192
#define ASTG  (4*AKT)                 // 32768 == 2*AQT
#define ATTN_SMEM (2*AQT + 2*ASTG)    // 98304
#define NKT   (TT/64)

// ---------------- cvt config ----------------
#define N4A (MTOT*D_MODEL/4)
#define N4W (D_MODEL*D_MODEL/4)
#define CVT_BLOCKS ((3*N4A + 4*N4W)/256)
#define SCL_BLOCKS (MTOT/256)

// -------- scratch (device globals; allocations forbidden) --------
__device__ __nv_bfloat16 g_xq_hi[(size_t)MTOT*D_MODEL], g_xq_lo[(size_t)MTOT*D_MODEL];
__device__ __nv_bfloat16 g_xk_hi[(size_t)MTOT*D_MODEL], g_xk_lo[(size_t)MTOT*D_MODEL];
__device__ __nv_bfloat16 g_xv_hi[(size_t)MTOT*D_MODEL], g_xv_lo[(size_t)MTOT*D_MODEL];
__device__ __nv_bfloat16 g_wq_hi[(size_t)D_MODEL*D_MODEL], g_wq_lo[(size_t)D_MODEL*D_MODEL];
__device__ __nv_bfloat16 g_wk_hi[(size_t)D_MODEL*D_MODEL], g_wk_lo[(size_t)D_MODEL*D_MODEL];
__device__ __nv_bfloat16 g_wv_hi[(size_t)D_MODEL*D_MODEL], g_wv_lo[(size_t)D_MODEL*D_MODEL];
__device__ __nv_bfloat16 g_wo_hi[(size_t)D_MODEL*D_MODEL], g_wo_lo[(size_t)D_MODEL*D_MODEL];
__device__ __nv_bfloat16 g_Qhi[(size_t)MTOT*D_MODEL], g_Qlo[(size_t)MTOT*D_MODEL];
__device__ __nv_bfloat16 g_Khi[(size_t)MTOT*D_MODEL], g_Klo[(size_t)MTOT*D_MODEL];
__device__ __nv_bfloat16 g_Vhi[(size_t)MTOT*D_MODEL], g_Vlo[(size_t)MTOT*D_MODEL];
__device__ __nv_bfloat16 g_Ahi[(size_t)MTOT*D_MODEL], g_Alo[(size_t)MTOT*D_MODEL];
__device__ float g_scl[MTOT];

// ---------------- helpers ----------------
__device__ __forceinline__ uint32_t smem_u32(const void* p) {
    uint32_t a;
    asm("{ .reg .u64 t; cvta.to.shared.u64 t, %1; cvt.u32.u64 %0, t; }" : "=r"(a) : "l"(p));
    return a;
}
__device__ __forceinline__ void ldsm4(uint32_t* r, uint32_t addr) {
    asm volatile("ldmatrix.sync.aligned.m8n8.x4.shared.b16 {%0,%1,%2,%3}, [%4];"
                 : "=r"(r[0]), "=r"(r[1]), "=r"(r[2]), "=r"(r[3]) : "r"(addr));
}
__device__ __forceinline__ void ldsm4t(uint32_t* r, uint32_t addr) {
    asm volatile("ldmatrix.sync.aligned.m8n8.x4.trans.shared.b16 {%0,%1,%2,%3}, [%4];"
                 : "=r"(r[0]), "=r"(r[1]), "=r"(r[2]), "=r"(r[3]) : "r"(addr));
}
__device__ __forceinline__ void mma_bf16(float* d, const uint32_t* a, const uint32_t* b) {
    asm volatile("mma.sync.aligned.m16n8k16.row.col.f32.bf16.bf16.f32 "
                 "{%0,%1,%2,%3}, {%4,%5,%6,%7}, {%8,%9}, {%0,%1,%2,%3};"
                 : "+f"(d[0]), "+f"(d[1]), "+f"(d[2]), "+f"(d[3])
                 : "r"(a[0]), "r"(a[1]), "r"(a[2]), "r"(a[3]), "r"(b[0]), "r"(b[1]));
}
__device__ __forceinline__ void cpa16(uint32_t dst, const void* src) {
    asm volatile("cp.async.cg.shared.global [%0], [%1], 16;" :: "r"(dst), "l"(src));
}
__device__ __forceinline__ void cp_commit() { asm volatile("cp.async.commit_group;"); }
template<int N> __device__ __forceinline__ void cp_wait() {
    asm volatile("cp.async.wait_group %0;" :: "n"(N));
}
__device__ __forceinline__ float ex2(float x) {
    float r;
    asm("ex2.approx.f32 %0, %1;" : "=f"(r) : "f"(x));
    return r;
}
__device__ __forceinline__ uint32_t bits(const __nv_bfloat162& h) {
    return *reinterpret_cast<const uint32_t*>(&h);
}
__device__ __forceinline__ void mk_hilo(uint32_t& hi, uint32_t& lo, float x, float y) {
    __nv_bfloat162 h = __floats2bfloat162_rn(x, y);
    float2 f = __bfloat1622float2(h);
    __nv_bfloat162 l = __floats2bfloat162_rn(x - f.x, y - f.y);
    hi = bits(h); lo = bits(l);
}

// ---------------------------------------------------------------------------
// One-shot conversion of all inputs + per-row scale, single launch.
// ---------------------------------------------------------------------------
__global__ void cvt_all_kernel(
    const float* __restrict__ q, const float* __restrict__ k, const float* __restrict__ v,
    const float* __restrict__ Wq, const float* __restrict__ Wk,
    const float* __restrict__ Wv, const float* __restrict__ Wo,
    const float* __restrict__ phi)
{
    const int bid = blockIdx.x;
    if (bid >= CVT_BLOCKS) {
        const int i = (bid - CVT_BLOCKS) * 256 + threadIdx.x;
        if (i < MTOT) {
            const float* p = phi + (size_t)i * 8;
            float s = 0.f;
#pragma unroll
            for (int f = 0; f < 8; f++) s += p[f];
            g_scl[i] = 1.0f / (8.0f * fmaxf(s * 0.125f, 1e-6f));
        }
        return;
    }
    const int gid = bid * 256 + threadIdx.x;
    const float* src; __nv_bfloat16 *hi, *lo; int idx;
    if (gid < N4A)            { src = q; hi = g_xq_hi; lo = g_xq_lo; idx = gid; }
    else if (gid < 2*N4A)     { src = k; hi = g_xk_hi; lo = g_xk_lo; idx = gid - N4A; }
    else if (gid < 3*N4A)     { src = v; hi = g_xv_hi; lo = g_xv_lo; idx = gid - 2*N4A; }
    else {
        const int w = gid - 3*N4A;
        if (w < N4W)          { src = Wq; hi = g_wq_hi; lo = g_wq_lo; idx = w; }
        else if (w < 2*N4W)   { src = Wk; hi = g_wk_hi; lo = g_wk_lo; idx = w - N4W; }
        else if (w < 3*N4W)   { src = Wv; hi = g_wv_hi; lo = g_wv_lo; idx = w - 2*N4W; }
        else                  { src = Wo; hi = g_wo_hi; lo = g_wo_lo; idx = w - 3*N4W; }
    }
    float4 x = ((const float4*)src)[idx];
    uint32_t h0, l0, h1, l1;
    mk_hilo(h0, l0, x.x, x.y);
    mk_hilo(h1, l1, x.z, x.w);
    ((uint2*)hi)[idx] = make_uint2(h0, h1);
    ((uint2*)lo)[idx] = make_uint2(l0, l1);
}

// ---------------------------------------------------------------------------
// HMMA split-bf16 GEMM. Whi fragments cached in registers across the 3 split
// terms (saves 2 ldmatrix.x4 per t per warp = -14% smem read traffic).
// Optional rowscale: C_row *= rowscale[row]*LOG2E before bf16 split (Q path).
// ---------------------------------------------------------------------------
__device__ __forceinline__ void hmma_gemm_bf16(
    const __nv_bfloat16* __restrict__ Ahi, const __nv_bfloat16* __restrict__ Alo,
    const __nv_bfloat16* __restrict__ Whi, const __nv_bfloat16* __restrict__ Wlo,
    const float* __restrict__ bias, const float* __restrict__ rowscale,
    float* __restrict__ Cf, __nv_bfloat16* __restrict__ Chi, __nv_bfloat16* __restrict__ Clo)
{
    extern __shared__ char sm[];
    const int tid  = threadIdx.x;
    const int lane = tid & 31;
    const int wid  = tid >> 5;
    const int wm   = wid & 1;
    const int wn   = wid >> 1;
    const int m0   = blockIdx.y * 128;
    const int n0   = blockIdx.x * 128;
    const uint32_t sb = smem_u32(sm);

    float d[4][4][4];
#pragma unroll
    for (int mt = 0; mt < 4; mt++)
#pragma unroll
        for (int nt = 0; nt < 4; nt++)
#pragma unroll
            for (int e = 0; e < 4; e++) d[mt][nt][e] = 0.f;

    const int lrow = tid >> 2;
    const int lch  = tid & 3;
    const uint32_t ldst0 = (uint32_t)(lrow * 64 + ((lch ^ ((lrow >> 1) & 3)) << 4));
    const size_t aoff = (size_t)(m0 + lrow) * D_MODEL + lch * 8;
    const size_t woff = (size_t)(n0 + lrow) * D_MODEL + lch * 8;
    const size_t R64  = (size_t)64 * D_MODEL;

    auto ISSUE = [&](int c) {
        const uint32_t st = sb + (c % 3) * GSTG;
        const int k0 = c * GKC;
        cpa16(st + 0*GOP + ldst0,        Ahi + aoff + k0);
        cpa16(st + 0*GOP + ldst0 + 4096, Ahi + aoff + R64 + k0);
        cpa16(st + 1*GOP + ldst0,        Alo + aoff + k0);
        cpa16(st + 1*GOP + ldst0 + 4096, Alo + aoff + R64 + k0);
        cpa16(st + 2*GOP + ldst0,        Whi + woff + k0);
        cpa16(st + 2*GOP + ldst0 + 4096, Whi + woff + R64 + k0);
        cpa16(st + 3*GOP + ldst0,        Wlo + woff + k0);
        cpa16(st + 3*GOP + ldst0 + 4096, Wlo + woff + R64 + k0);
    };

    const int a_hi = lane >> 4;
    const int b_c  = (lane >> 3) & 1;
    uint32_t a_rb[4], b_rb[2];
    int a_rm[4], b_rm[2];
#pragma unroll
    for (int mt = 0; mt < 4; mt++) {
        int row = wm*64 + mt*16 + (lane & 15);
        a_rb[mt] = row * 64; a_rm[mt] = (row >> 1) & 3;
    }
#pragma unroll
    for (int nh = 0; nh < 2; nh++) {
        int row = wn*32 + nh*16 + (lane & 7) + ((lane >> 4) << 3);
        b_rb[nh] = row * 64; b_rm[nh] = (row >> 1) & 3;
    }

    auto LD_A = [&](uint32_t opbase, int t, uint32_t af[4][4]) {
#pragma unroll
        for (int mt = 0; mt < 4; mt++)
            ldsm4(af[mt], opbase + a_rb[mt] + ((((t<<1)|a_hi) ^ a_rm[mt]) << 4));
    };
    auto LD_B = [&](uint32_t opbase, int t, uint32_t bf[4][2]) {
#pragma unroll
        for (int nh = 0; nh < 2; nh++) {
            uint32_t r[4];
            ldsm4(r, opbase + b_rb[nh] + ((((t<<1)|b_c) ^ b_rm[nh]) << 4));
            bf[nh*2+0][0] = r[0]; bf[nh*2+0][1] = r[1];
            bf[nh*2+1][0] = r[2]; bf[nh*2+1][1] = r[3];
        }
    };
    auto MMA16 = [&](const uint32_t af[4][4], const uint32_t bf[4][2]) {
#pragma unroll
        for (int mt = 0; mt < 4; mt++)
#pragma unroll
            for (int nt = 0; nt < 4; nt++)
                mma_bf16(d[mt][nt], af[mt], bf[nt]);
    };
    auto MMA_CHUNK = [&](int stg) {
        const uint32_t base = sb + stg * GSTG;
        uint32_t af[4][4], bh[4][2], bl[4][2];
#pragma unroll
        for (int t = 0; t < 2; t++) {
            LD_A(base + 0*GOP, t, af);      // A hi
            LD_B(base + 2*GOP, t, bh);      // W hi (kept live)
            MMA16(af, bh);                  // hh
            LD_B(base + 3*GOP, t, bl);      // W lo
            MMA16(af, bl);                  // hl
            LD_A(base + 1*GOP, t, af);      // A lo (overwrite)
            MMA16(af, bh);                  // lh (cached Whi — no reload)
        }
    };

    ISSUE(0); cp_commit();
    ISSUE(1); cp_commit();
    for (int c = 0; c < GNCH; c++) {
        cp_wait<1>();
        __syncthreads();
        MMA_CHUNK(c % 3);
        if (c + 2 < GNCH) ISSUE(c + 2);
        cp_commit();
    }

    const int g = lane >> 2, tq = lane & 3;
#pragma unroll
    for (int mt = 0; mt < 4; mt++) {
#pragma unroll
        for (int nt = 0; nt < 4; nt++) {
            const int row = m0 + wm*64 + mt*16 + g;
            const int col = n0 + wn*32 + nt*8 + tq*2;
            const float b0 = bias[col], b1 = bias[col + 1];
            float c0 = d[mt][nt][0] + b0, c1 = d[mt][nt][1] + b1;
            float c2 = d[mt][nt][2] + b0, c3 = d[mt][nt][3] + b1;
            if (rowscale) {
                const float s0 = rowscale[row]     * LOG2E;
                const float s1 = rowscale[row + 8] * LOG2E;
                c0 *= s0; c1 *= s0; c2 *= s1; c3 *= s1;
            }
            if (Cf) {
                *(float2*)&Cf[(size_t)row * D_MODEL + col]       = make_float2(c0, c1);
                *(float2*)&Cf[(size_t)(row + 8) * D_MODEL + col] = make_float2(c2, c3);
            } else {
                uint32_t h, l;
                mk_hilo(h, l, c0, c1);
                *(uint32_t*)&Chi[(size_t)row * D_MODEL + col] = h;
                *(uint32_t*)&Clo[(size_t)row * D_MODEL + col] = l;
                mk_hilo(h, l, c2, c3);
                *(uint32_t*)&Chi[(size_t)(row + 8) * D_MODEL + col] = h;
                *(uint32_t*)&Clo[(size_t)(row + 8) * D_MODEL + col] = l;
            }
        }
    }
}

__global__ __launch_bounds__(256, 2) void tc_qkv_kernel(
    const float* __restrict__ bq, const float* __restrict__ bk, const float* __restrict__ bv)
{
    if (blockIdx.z == 0)   // Q: fold rowscale*log2e so attention uses bare ex2
        hmma_gemm_bf16(g_xq_hi, g_xq_lo, g_wq_hi, g_wq_lo, bq, g_scl, nullptr, g_Qhi, g_Qlo);
    else if (blockIdx.z == 1)
        hmma_gemm_bf16(g_xk_hi, g_xk_lo, g_wk_hi, g_wk_lo, bk, nullptr, nullptr, g_Khi, g_Klo);
    else
        hmma_gemm_bf16(g_xv_hi, g_xv_lo, g_wv_hi, g_wv_lo, bv, nullptr, nullptr, g_Vhi, g_Vlo);
}

__global__ __launch_bounds__(256, 2) void tc_out_kernel(
    const float* __restrict__ bo, float* __restrict__ out)
{
    hmma_gemm_bf16(g_Ahi, g_Alo, g_wo_hi, g_wo_lo, bo, nullptr, out, nullptr, nullptr);
}

// ---------------------------------------------------------------------------
// HMMA flash attention, no-max softmax with scale pre-folded into Q.
// 3-stage KV pipeline in 2-stage footprint (Q smem region reused as stage 2),
// single __syncthreads per tile. p = ex2(s) directly.
// ---------------------------------------------------------------------------
__global__ __launch_bounds__(256, 2) void attn_mma_kernel()
{
    extern __shared__ char sm[];
    const int tid  = threadIdx.x;
    const int lane = tid & 31;
    const int wid  = tid >> 5;
    const int b    = blockIdx.z, h = blockIdx.y;
    const int q0   = blockIdx.x * 128;
    const uint32_t sb  = smem_u32(sm);
    const uint32_t kvb = sb + 2*AQT;
    const size_t hoff = (size_t)h * HD;

    auto STADDR = [&](int s) -> uint32_t {
        return (s == 2) ? sb : kvb + (uint32_t)s * ASTG;
    };

    // ---- Q tile cp.async (group 0) ----
    {
        const int qrow = tid >> 3;
        const int qch  = tid & 7;
        const uint32_t qd = (uint32_t)(qrow * 128 + ((qch ^ (qrow & 7)) << 4));
        const size_t qsrc = (size_t)(b*TT + q0 + qrow) * D_MODEL + hoff + qch * 8;
        const size_t R32 = (size_t)32 * D_MODEL;
#pragma unroll
        for (int j = 0; j < 4; j++) {
            cpa16(sb + qd + j*4096,       g_Qhi + qsrc + j*R32);
            cpa16(sb + AQT + qd + j*4096, g_Qlo + qsrc + j*R32);
        }
        cp_commit();
    }

    const int krow = tid >> 3;
    const int kch  = tid & 7;
    const uint32_t kd0 = (uint32_t)(krow * 128 + ((kch ^ (krow & 7)) << 4));
    const size_t koff = (size_t)(b*TT + krow) * D_MODEL + hoff + kch * 8;
    const size_t R32  = (size_t)32 * D_MODEL;
    const size_t TSTEP = (size_t)64 * D_MODEL;

    auto ISSUEKV = [&](int c) {
        const uint32_t st = STADDR(c % 3);
        const size_t s0 = koff + (size_t)c * TSTEP;
        cpa16(st + 0*AKT + kd0,        g_Khi + s0);
        cpa16(st + 0*AKT + kd0 + 4096, g_Khi + s0 + R32);
        cpa16(st + 1*AKT + kd0,        g_Klo + s0);
        cpa16(st + 1*AKT + kd0 + 4096, g_Klo + s0 + R32);
        cpa16(st + 2*AKT + kd0,        g_Vhi + s0);
        cpa16(st + 2*AKT + kd0 + 4096, g_Vhi + s0 + R32);
        cpa16(st + 3*AKT + kd0,        g_Vlo + s0);
        cpa16(st + 3*AKT + kd0 + 4096, g_Vlo + s0 + R32);
    };

    ISSUEKV(0); cp_commit();
    ISSUEKV(1); cp_commit();

    cp_wait<2>();
    __syncthreads();

    uint32_t qh[4][4], ql[4][4];
    {
        const int qr  = wid*16 + (lane & 15);
        const uint32_t qrb = (uint32_t)qr * 128;
        const int qrm = qr & 7;
        const int qhi = lane >> 4;
#pragma unroll
        for (int kc = 0; kc < 4; kc++) {
            ldsm4(qh[kc], sb       + qrb + ((((kc<<1)|qhi) ^ qrm) << 4));
            ldsm4(ql[kc], sb + AQT + qrb + ((((kc<<1)|qhi) ^ qrm) << 4));
        }
    }
    // stage 2 (Q region) first overwritten by ISSUEKV(2) — after c=0 barrier.

    const int g = lane >> 2;
    float l0 = 0.f, l1 = 0.f;
    float o[8][4];
#pragma unroll
    for (int dn = 0; dn < 8; dn++)
#pragma unroll
        for (int e = 0; e < 4; e++) o[dn][e] = 0.f;

    const int b_c = (lane >> 3) & 1;
    uint32_t k_rb[4]; int k_rm[4];
#pragma unroll
    for (int nq = 0; nq < 4; nq++) {
        int row = nq*16 + (lane & 7) + ((lane >> 4) << 3);
        k_rb[nq] = row * 128; k_rm[nq] = row & 7;
    }
    const int v_hi = lane >> 4;
    uint32_t v_rb[4]; int v_rm[4];
#pragma unroll
    for (int kc = 0; kc < 4; kc++) {
        int row = kc*16 + (lane & 15);
        v_rb[kc] = row * 128; v_rm[kc] = row & 7;
    }

    auto COMPUTE = [&](uint32_t kh) {
        const uint32_t kl = kh + AKT;
        const uint32_t vh = kh + 2*AKT;
        const uint32_t vl = kh + 3*AKT;

        // ---- S = Q K^T (3-MMA split; Q pre-scaled by rs*log2e) ----
        float s[8][4];
#pragma unroll
        for (int nt = 0; nt < 8; nt++)
#pragma unroll
            for (int e = 0; e < 4; e++) s[nt][e] = 0.f;

#pragma unroll
        for (int kc = 0; kc < 4; kc++) {
#pragma unroll
            for (int nq = 0; nq < 4; nq++) {
                const uint32_t co = ((((kc<<1)|b_c) ^ k_rm[nq]) << 4);
                uint32_t r[4];
                ldsm4(r, kh + k_rb[nq] + co);
                uint32_t b0[2] = { r[0], r[1] }, b1[2] = { r[2], r[3] };
                mma_bf16(s[2*nq],   qh[kc], b0);
                mma_bf16(s[2*nq+1], qh[kc], b1);
                mma_bf16(s[2*nq],   ql[kc], b0);
                mma_bf16(s[2*nq+1], ql[kc], b1);
                ldsm4(r, kl + k_rb[nq] + co);
                uint32_t c0[2] = { r[0], r[1] }, c1[2] = { r[2], r[3] };
                mma_bf16(s[2*nq],   qh[kc], c0);
                mma_bf16(s[2*nq+1], qh[kc], c1);
            }
        }

        // ---- softmax: p = 2^s directly (scale folded into Q) ----
#pragma unroll
        for (int nt = 0; nt < 8; nt++) {
            s[nt][0] = ex2(s[nt][0]);
            s[nt][1] = ex2(s[nt][1]);
            s[nt][2] = ex2(s[nt][2]);
            s[nt][3] = ex2(s[nt][3]);
            l0 += s[nt][0] + s[nt][1];
            l1 += s[nt][2] + s[nt][3];
        }

        // ---- O += P V (3-MMA split), V via trans ldmatrix ----
#pragma unroll
        for (int kc = 0; kc < 4; kc++) {
            uint32_t ah[4], al[4];
            mk_hilo(ah[0], al[0], s[2*kc][0],   s[2*kc][1]);
            mk_hilo(ah[1], al[1], s[2*kc][2],   s[2*kc][3]);
            mk_hilo(ah[2], al[2], s[2*kc+1][0], s[2*kc+1][1]);
            mk_hilo(ah[3], al[3], s[2*kc+1][2], s[2*kc+1][3]);
#pragma unroll
            for (int dq = 0; dq < 4; dq++) {
                const uint32_t co = ((((dq<<1)|v_hi) ^ v_rm[kc]) << 4);
                uint32_t r[4];
                ldsm4t(r, vh + v_rb[kc] + co);
                uint32_t b0[2] = { r[0], r[1] }, b1[2] = { r[2], r[3] };
                mma_bf16(o[2*dq],   ah, b0);
                mma_bf16(o[2*dq+1], ah, b1);
                mma_bf16(o[2*dq],   al, b0);
                mma_bf16(o[2*dq+1], al, b1);
                ldsm4t(r, vl + v_rb[kc] + co);
                uint32_t c0[2] = { r[0], r[1] }, c1[2] = { r[2], r[3] };
                mma_bf16(o[2*dq],   ah, c0);
                mma_bf16(o[2*dq+1], ah, c1);
            }
        }
    };

    // ---- main loop: 3-stage, ONE sync per tile ----
    for (int c = 0; c < NKT; c++) {
        cp_wait<1>();
        __syncthreads();
        COMPUTE(STADDR(c % 3));
        if (c + 2 < NKT) ISSUEKV(c + 2);
        cp_commit();
    }

    // ---- end-of-loop row-sum reduction ----
    l0 += __shfl_xor_sync(0xffffffffu, l0, 1);
    l0 += __shfl_xor_sync(0xffffffffu, l0, 2);
    l1 += __shfl_xor_sync(0xffffffffu, l1, 1);
    l1 += __shfl_xor_sync(0xffffffffu, l1, 2);

    // ---- normalize & write split-bf16 head output ----
    const float inv0 = 1.0f / l0, inv1 = 1.0f / l1;
    const int t2 = (lane & 3) * 2;
    const size_t row0 = (size_t)(b*TT + q0 + wid*16 + g);
#pragma unroll
    for (int dn = 0; dn < 8; dn++) {
        uint32_t hb, lb;
        mk_hilo(hb, lb, o[dn][0]*inv0, o[dn][1]*inv0);
        *(uint32_t*)&g_Ahi[row0 * D_MODEL + hoff + dn*8 + t2] = hb;
        *(uint32_t*)&g_Alo[row0 * D_MODEL + hoff + dn*8 + t2] = lb;
        mk_hilo(hb, lb, o[dn][2]*inv1, o[dn][3]*inv1);
        *(uint32_t*)&g_Ahi[(row0 + 8) * D_MODEL + hoff + dn*8 + t2] = hb;
        *(uint32_t*)&g_Alo[(row0 + 8) * D_MODEL + hoff + dn*8 + t2] = lb;
    }
}

// ---------------------------------------------------------------------------
extern "C" void kernel_launch(void* const* d_in, const int* in_sizes, int n_in,
                              void* d_out, int out_size)
{
    const float* query = (const float*)d_in[0];
    const float* key   = (const float*)d_in[1];
    const float* value = (const float*)d_in[2];
    const float* phi   = (const float*)d_in[3];
    // d_in[4] logvar, d_in[13] w_sigma, d_in[14] w_phi: cancel under softmax
    const float* Wq = (const float*)d_in[5];
    const float* bq = (const float*)d_in[6];
    const float* Wk = (const float*)d_in[7];
    const float* bk = (const float*)d_in[8];
    const float* Wv = (const float*)d_in[9];
    const float* bv = (const float*)d_in[10];
    const float* Wo = (const float*)d_in[11];
    const float* bo = (const float*)d_in[12];
    float* out = (float*)d_out;

    cudaFuncSetAttribute(tc_qkv_kernel,   cudaFuncAttributeMaxDynamicSharedMemorySize, GEMM_SMEM);
    cudaFuncSetAttribute(tc_out_kernel,   cudaFuncAttributeMaxDynamicSharedMemorySize, GEMM_SMEM);
    cudaFuncSetAttribute(attn_mma_kernel, cudaFuncAttributeMaxDynamicSharedMemorySize, ATTN_SMEM);

    cvt_all_kernel<<<CVT_BLOCKS + SCL_BLOCKS, 256>>>(query, key, value, Wq, Wk, Wv, Wo, phi);
    tc_qkv_kernel<<<dim3(D_MODEL/128, MTOT/128, 3), 256, GEMM_SMEM>>>(bq, bk, bv);
    attn_mma_kernel<<<dim3(TT/128, HEADS, BB), 256, ATTN_SMEM>>>();
    tc_out_kernel<<<dim3(D_MODEL/128, MTOT/128, 1), 256, GEMM_SMEM>>>(bo, out);
}